// round 11
// baseline (speedup 1.0000x reference)
#include <cuda_runtime.h>
#include <cuda_fp16.h>
#include <math.h>
#include <stdint.h>

#define T_TOK 1024
#define HID   2048
#define NEXP  16
#define TOPK  4
#define IEXP  1408
#define ISH   2816

#define W1_ELEMS  ((size_t)NEXP * 2 * IEXP * HID)
#define W1_HALF   (W1_ELEMS / 2)                    // experts 0..7
#define W2_ELEMS  ((size_t)NEXP * HID * IEXP)
#define WSG_ELEMS ((size_t)2 * ISH * HID)
#define WSD_ELEMS ((size_t)HID * ISH)

// ---------------- scratch (__device__ globals) ----------------
__device__ __align__(1024) __half g_w1h[W1_ELEMS];
__device__ __align__(1024) __half g_w2h[W2_ELEMS];
__device__ __align__(1024) __half g_wsgh[WSG_ELEMS];
__device__ __align__(1024) __half g_wsdh[WSD_ELEMS];
__device__ __align__(1024) __half g_xh[(size_t)T_TOK * HID];
__device__ __align__(1024) __half g_xg[(size_t)NEXP * T_TOK * HID];
__device__ __align__(1024) __half g_acth[(size_t)NEXP * T_TOK * IEXP];
__device__ __align__(1024) __half g_ashh[(size_t)T_TOK * ISH];
__device__ float g_ysc[(size_t)NEXP * T_TOK * HID];
__device__ float g_sout[(size_t)T_TOK * HID];
__device__ int   g_cnt[NEXP];
__device__ int   g_te[T_TOK * TOPK];
__device__ int   g_slot[T_TOK * TOPK];
__device__ float g_tw[T_TOK * TOPK];

// ---------------- PTX helpers ----------------
__device__ __forceinline__ uint32_t smem_u32(const void* p) {
    uint32_t a;
    asm("{ .reg .u64 t; cvta.to.shared.u64 t, %1; cvt.u32.u64 %0, t; }" : "=r"(a) : "l"(p));
    return a;
}
#define CP16(dst, src) asm volatile("cp.async.cg.shared.global [%0], [%1], 16;" :: "r"(dst), "l"(src) : "memory")
#define CPCOMMIT()     asm volatile("cp.async.commit_group;" ::: "memory")
#define CPWAIT(n)      asm volatile("cp.async.wait_group %0;" :: "n"(n) : "memory")

__device__ __forceinline__ void ldsm4(uint32_t addr, uint32_t& r0, uint32_t& r1,
                                      uint32_t& r2, uint32_t& r3) {
    asm volatile("ldmatrix.sync.aligned.m8n8.x4.shared.b16 {%0,%1,%2,%3}, [%4];"
                 : "=r"(r0), "=r"(r1), "=r"(r2), "=r"(r3) : "r"(addr));
}
__device__ __forceinline__ void mma16816(float* c, uint32_t a0, uint32_t a1, uint32_t a2,
                                         uint32_t a3, uint32_t b0, uint32_t b1) {
    asm volatile(
        "mma.sync.aligned.m16n8k16.row.col.f32.f16.f16.f32 "
        "{%0,%1,%2,%3}, {%4,%5,%6,%7}, {%8,%9}, {%0,%1,%2,%3};"
        : "+f"(c[0]), "+f"(c[1]), "+f"(c[2]), "+f"(c[3])
        : "r"(a0), "r"(a1), "r"(a2), "r"(a3), "r"(b0), "r"(b1));
}

#define SWZ(o) ((o) ^ (((o) >> 3) & 0x70))
#define NSTAGE 3
#define STAGE_B 32768
#define SMEM_DYN (NSTAGE * STAGE_B + 1024)

// convert 8 contiguous fp32 -> 8 fp16 (gmem->gmem)
__device__ __forceinline__ void cvt8(const float* s, __half* d) {
    float4 a = *(const float4*)s;
    float4 b = *(const float4*)(s + 4);
    __half2 h0 = __floats2half2_rn(a.x, a.y), h1 = __floats2half2_rn(a.z, a.w);
    __half2 h2 = __floats2half2_rn(b.x, b.y), h3 = __floats2half2_rn(b.z, b.w);
    uint4 o;
    o.x = *(uint32_t*)&h0; o.y = *(uint32_t*)&h1; o.z = *(uint32_t*)&h2; o.w = *(uint32_t*)&h3;
    *(uint4*)d = o;
}

__global__ void zero_kernel() { if (threadIdx.x < NEXP) g_cnt[threadIdx.x] = 0; }

// ---------------- router (+x->fp16+gather) with conv(Wsg) blocks appended ----------------
#define NCR 192
__global__ void router_kernel(const float* __restrict__ x, const float* __restrict__ Wg,
                              const float* __restrict__ Wsg, __half* __restrict__ wsgh) {
    if (blockIdx.x >= T_TOK) {
        // conv Wsg role: 128 threads x 8 elems = 1024 per iter
        int cb = blockIdx.x - T_TOK;
        size_t chunk = ((WSG_ELEMS + (size_t)NCR * 1024 - 1) / ((size_t)NCR * 1024)) * 1024;
        size_t start = (size_t)cb * chunk;
        size_t end = start + chunk; if (end > WSG_ELEMS) end = WSG_ELEMS;
        for (size_t off = start + threadIdx.x * 8; off < end; off += 1024)
            cvt8(Wsg + off, wsgh + off);
        return;
    }
    int t = blockIdx.x;
    const float* xr = x + (size_t)t * HID;
    float acc[NEXP];
#pragma unroll
    for (int e = 0; e < NEXP; e++) acc[e] = 0.f;
    for (int h = threadIdx.x; h < HID; h += 128) {
        float xv = xr[h];
        const float* wr = Wg + (size_t)h * NEXP;
#pragma unroll
        for (int e = 0; e < NEXP; e++) acc[e] = fmaf(xv, wr[e], acc[e]);
    }
    __shared__ float red[128 * NEXP];
#pragma unroll
    for (int e = 0; e < NEXP; e++) red[threadIdx.x * NEXP + e] = acc[e];
    __syncthreads();
    __shared__ float logits[NEXP];
    if (threadIdx.x < NEXP) {
        float s = 0.f;
        for (int i = 0; i < 128; i++) s += red[i * NEXP + threadIdx.x];
        logits[threadIdx.x] = s;
    }
    __syncthreads();
    __shared__ int s_e[TOPK], s_sl[TOPK];
    if (threadIdx.x == 0) {
        float lv[NEXP];
#pragma unroll
        for (int e = 0; e < NEXP; e++) lv[e] = logits[e];
        int ids[TOPK]; float vals[TOPK];
        bool used[NEXP];
#pragma unroll
        for (int e = 0; e < NEXP; e++) used[e] = false;
        for (int k = 0; k < TOPK; k++) {
            int bi = 0; float bv = -3.4e38f;
            for (int e = 0; e < NEXP; e++)
                if (!used[e] && lv[e] > bv) { bv = lv[e]; bi = e; }
            used[bi] = true; ids[k] = bi; vals[k] = bv;
        }
        float m = vals[0], ssum = 0.f, wv[TOPK];
        for (int k = 0; k < TOPK; k++) { wv[k] = expf(vals[k] - m); ssum += wv[k]; }
        float inv = 1.f / ssum;
        for (int k = 0; k < TOPK; k++) {
            int e = ids[k];
            int slot = atomicAdd(&g_cnt[e], 1);
            g_te[t * TOPK + k]   = e;
            g_slot[t * TOPK + k] = slot;
            g_tw[t * TOPK + k]   = wv[k] * inv;
            s_e[k] = e; s_sl[k] = slot;
        }
    }
    __syncthreads();
    int tid = threadIdx.x;
    const float4* xr4 = (const float4*)xr;
    float4 f0 = xr4[tid * 4 + 0], f1 = xr4[tid * 4 + 1];
    float4 f2 = xr4[tid * 4 + 2], f3 = xr4[tid * 4 + 3];
    __half2 h0 = __floats2half2_rn(f0.x, f0.y), h1 = __floats2half2_rn(f0.z, f0.w);
    __half2 h2 = __floats2half2_rn(f1.x, f1.y), h3 = __floats2half2_rn(f1.z, f1.w);
    __half2 h4 = __floats2half2_rn(f2.x, f2.y), h5 = __floats2half2_rn(f2.z, f2.w);
    __half2 h6 = __floats2half2_rn(f3.x, f3.y), h7 = __floats2half2_rn(f3.z, f3.w);
    uint4 u0 = make_uint4(*(uint32_t*)&h0, *(uint32_t*)&h1, *(uint32_t*)&h2, *(uint32_t*)&h3);
    uint4 u1 = make_uint4(*(uint32_t*)&h4, *(uint32_t*)&h5, *(uint32_t*)&h6, *(uint32_t*)&h7);
    uint4* dh = (uint4*)(g_xh + (size_t)t * HID) + tid * 2;
    dh[0] = u0; dh[1] = u1;
#pragma unroll
    for (int k = 0; k < TOPK; k++) {
        uint4* dg = (uint4*)(g_xg + ((size_t)s_e[k] * T_TOK + s_sl[k]) * HID) + tid * 2;
        dg[0] = u0; dg[1] = u1;
    }
}

// ---------------- gemm1 carrier: fp16 GEMM blocks + Bresenham-interleaved conv blocks ------
// shared_mode=1: gemm1 on shared MLP. else experts [e_base, e_base+8).
__global__ void __launch_bounds__(256) gemm1_mma(int shared_mode, int e_base, int NG, int NC,
                                                 const float* __restrict__ ca, __half* __restrict__ cda, size_t na,
                                                 const float* __restrict__ cb, __half* __restrict__ cdb, size_t nb) {
    uint32_t bx = blockIdx.x;
    uint32_t N = (uint32_t)(NG + NC);
    uint32_t cle = (uint32_t)(((uint64_t)(bx + 1) * (uint32_t)NC) / N);
    uint32_t clt = (uint32_t)(((uint64_t)bx * (uint32_t)NC) / N);
    if (cle > clt) {
        size_t total = na + nb;
        size_t chunk = ((total + (size_t)NC * 2048 - 1) / ((size_t)NC * 2048)) * 2048;
        size_t start = (size_t)clt * chunk;
        size_t end = start + chunk; if (end > total) end = total;
        for (size_t off = start + threadIdx.x * 8; off < end; off += 2048) {
            if (off < na) cvt8(ca + off, cda + off);
            else          cvt8(cb + (off - na), cdb + (off - na));
        }
        return;
    }
    uint32_t gidx = bx - cle;

    const __half* A; const __half* B; __half* act;
    int nrows, Ihalf;
    const int K = HID;
    int JX = shared_mode ? (ISH / 64) : (IEXP / 64);
    int gx = (int)(gidx % (uint32_t)JX);
    uint32_t rem = gidx / (uint32_t)JX;
    int gy = (int)(rem & 7);
    if (shared_mode) {
        A = g_xh; B = g_wsgh; act = g_ashh; nrows = T_TOK; Ihalf = ISH;
    } else {
        int e = e_base + (int)(rem >> 3);
        A = g_xg + (size_t)e * T_TOK * HID;
        B = g_w1h + (size_t)e * 2 * IEXP * HID;
        act = g_acth + (size_t)e * T_TOK * IEXP;
        nrows = g_cnt[e]; Ihalf = IEXP;
    }
    int m0 = gy * 128;
    if (m0 >= nrows) return;
    int j0 = gx * 64;

    extern __shared__ char smraw[];
    uint32_t sb = (smem_u32(smraw) + 1023) & ~1023u;
    int tid = threadIdx.x, lane = tid & 31, wid = tid >> 5;
    int wm = wid & 3, wn = wid >> 2;

    const __half* asrc[4]; const __half* bsrc[4]; uint32_t swz[4];
#pragma unroll
    for (int i = 0; i < 4; i++) {
        int row = (tid >> 3) + 32 * i;
        int c16 = tid & 7;
        asrc[i] = A + (size_t)(m0 + row) * K + c16 * 8;
        int brow = (row < 64) ? (j0 + row) : (Ihalf + j0 + row - 64);
        bsrc[i] = B + (size_t)brow * K + c16 * 8;
        swz[i] = SWZ((uint32_t)(row * 128 + c16 * 16));
    }

    const int KT = K / 64;
    for (int s = 0; s < NSTAGE - 1; s++) {
        uint32_t sA = sb + s * STAGE_B, sB = sA + 16384;
        int ko = s * 64;
#pragma unroll
        for (int i = 0; i < 4; i++) { CP16(sA + swz[i], asrc[i] + ko); CP16(sB + swz[i], bsrc[i] + ko); }
        CPCOMMIT();
    }

    float ct[2][8][4];
#pragma unroll
    for (int mi = 0; mi < 2; mi++)
#pragma unroll
        for (int j = 0; j < 8; j++)
#pragma unroll
            for (int q = 0; q < 4; q++) ct[mi][j][q] = 0.f;

    uint32_t l15 = (uint32_t)(lane & 15);
    uint32_t kcb = ((lane >> 4) << 4);

    for (int kt = 0; kt < KT; kt++) {
        CPWAIT(1);
        __syncthreads();
        uint32_t sA = sb + (kt % NSTAGE) * STAGE_B, sB = sA + 16384;
#pragma unroll
        for (int ks = 0; ks < 4; ks++) {
            uint32_t a0[4], a1[4];
            ldsm4(sA + SWZ((uint32_t)((wm * 32 + l15) * 128) + ks * 32 + kcb), a0[0], a0[1], a0[2], a0[3]);
            ldsm4(sA + SWZ((uint32_t)((wm * 32 + 16 + l15) * 128) + ks * 32 + kcb), a1[0], a1[1], a1[2], a1[3]);
#pragma unroll
            for (int bb = 0; bb < 2; bb++) {
                uint32_t b0, b1, b2, b3;
                ldsm4(sB + SWZ((uint32_t)((wn * 32 + bb * 16 + l15) * 128) + ks * 32 + kcb), b0, b1, b2, b3);
                mma16816(ct[0][2 * bb],     a0[0], a0[1], a0[2], a0[3], b0, b2);
                mma16816(ct[0][2 * bb + 1], a0[0], a0[1], a0[2], a0[3], b1, b3);
                mma16816(ct[1][2 * bb],     a1[0], a1[1], a1[2], a1[3], b0, b2);
                mma16816(ct[1][2 * bb + 1], a1[0], a1[1], a1[2], a1[3], b1, b3);
            }
#pragma unroll
            for (int bb = 0; bb < 2; bb++) {
                uint32_t b0, b1, b2, b3;
                ldsm4(sB + SWZ((uint32_t)((64 + wn * 32 + bb * 16 + l15) * 128) + ks * 32 + kcb), b0, b1, b2, b3);
                mma16816(ct[0][4 + 2 * bb],     a0[0], a0[1], a0[2], a0[3], b0, b2);
                mma16816(ct[0][4 + 2 * bb + 1], a0[0], a0[1], a0[2], a0[3], b1, b3);
                mma16816(ct[1][4 + 2 * bb],     a1[0], a1[1], a1[2], a1[3], b0, b2);
                mma16816(ct[1][4 + 2 * bb + 1], a1[0], a1[1], a1[2], a1[3], b1, b3);
            }
        }
        __syncthreads();
        int nc = kt + NSTAGE - 1;
        if (nc < KT) {
            uint32_t dA = sb + (nc % NSTAGE) * STAGE_B, dB = dA + 16384;
            int ko = nc * 64;
#pragma unroll
            for (int i = 0; i < 4; i++) { CP16(dA + swz[i], asrc[i] + ko); CP16(dB + swz[i], bsrc[i] + ko); }
        }
        CPCOMMIT();
    }

#pragma unroll
    for (int mi = 0; mi < 2; mi++) {
        int row = m0 + wm * 32 + mi * 16 + (lane >> 2);
#pragma unroll
        for (int ni = 0; ni < 4; ni++) {
            int col = j0 + wn * 32 + ni * 8 + (lane & 3) * 2;
            if (row < nrows) {
                float g0 = ct[mi][ni][0], g1 = ct[mi][ni][1];
                float u0 = ct[mi][ni + 4][0], u1 = ct[mi][ni + 4][1];
                __half2 h = __floats2half2_rn(g0 / (1.f + expf(-g0)) * u0,
                                              g1 / (1.f + expf(-g1)) * u1);
                *(__half2*)(act + (size_t)row * Ihalf + col) = h;
            }
            if (row + 8 < nrows) {
                float g0 = ct[mi][ni][2], g1 = ct[mi][ni][3];
                float u0 = ct[mi][ni + 4][2], u1 = ct[mi][ni + 4][3];
                __half2 h = __floats2half2_rn(g0 / (1.f + expf(-g0)) * u0,
                                              g1 / (1.f + expf(-g1)) * u1);
                *(__half2*)(act + (size_t)(row + 8) * Ihalf + col) = h;
            }
        }
    }
}

// ---------------- gemm2 combined: flattened grid = 128 shared blocks + 2048 expert blocks ----
#define G2_SH_BLK ((HID / 128) * (T_TOK / 128))                 // 128
#define G2_EX_BLK ((HID / 128) * (T_TOK / 128) * NEXP)          // 2048
__global__ void __launch_bounds__(256) gemm2_mma() {
    uint32_t bx = blockIdx.x;
    const __half* A; const __half* B; float* C;
    int nrows, K, gx, gy;
    if (bx < G2_SH_BLK) {
        A = g_ashh; B = g_wsdh; C = g_sout; nrows = T_TOK; K = ISH;
        gx = (int)(bx & 15); gy = (int)(bx >> 4);
    } else {
        uint32_t i = bx - G2_SH_BLK;
        gx = (int)(i & 15);
        uint32_t rem = i >> 4;
        gy = (int)(rem & 7);
        int e = (int)(rem >> 3);
        A = g_acth + (size_t)e * T_TOK * IEXP;
        B = g_w2h + (size_t)e * HID * IEXP;
        C = g_ysc + (size_t)e * T_TOK * HID;
        nrows = g_cnt[e]; K = IEXP;
    }
    int m0 = gy * 128;
    if (m0 >= nrows) return;
    int n0 = gx * 128;

    extern __shared__ char smraw[];
    uint32_t sb = (smem_u32(smraw) + 1023) & ~1023u;
    int tid = threadIdx.x, lane = tid & 31, wid = tid >> 5;
    int wm = wid & 3, wn = wid >> 2;

    const __half* asrc[4]; const __half* bsrc[4]; uint32_t swz[4];
#pragma unroll
    for (int i = 0; i < 4; i++) {
        int row = (tid >> 3) + 32 * i;
        int c16 = tid & 7;
        asrc[i] = A + (size_t)(m0 + row) * K + c16 * 8;
        bsrc[i] = B + (size_t)(n0 + row) * K + c16 * 8;
        swz[i] = SWZ((uint32_t)(row * 128 + c16 * 16));
    }

    const int KT = K / 64;
    for (int s = 0; s < NSTAGE - 1; s++) {
        uint32_t sA = sb + s * STAGE_B, sB = sA + 16384;
        int ko = s * 64;
#pragma unroll
        for (int i = 0; i < 4; i++) { CP16(sA + swz[i], asrc[i] + ko); CP16(sB + swz[i], bsrc[i] + ko); }
        CPCOMMIT();
    }

    float ct[2][8][4];
#pragma unroll
    for (int mi = 0; mi < 2; mi++)
#pragma unroll
        for (int j = 0; j < 8; j++)
#pragma unroll
            for (int q = 0; q < 4; q++) ct[mi][j][q] = 0.f;

    uint32_t l15 = (uint32_t)(lane & 15);
    uint32_t kcb = ((lane >> 4) << 4);

    for (int kt = 0; kt < KT; kt++) {
        CPWAIT(1);
        __syncthreads();
        uint32_t sA = sb + (kt % NSTAGE) * STAGE_B, sB = sA + 16384;
#pragma unroll
        for (int ks = 0; ks < 4; ks++) {
            uint32_t a0[4], a1[4];
            ldsm4(sA + SWZ((uint32_t)((wm * 32 + l15) * 128) + ks * 32 + kcb), a0[0], a0[1], a0[2], a0[3]);
            ldsm4(sA + SWZ((uint32_t)((wm * 32 + 16 + l15) * 128) + ks * 32 + kcb), a1[0], a1[1], a1[2], a1[3]);
#pragma unroll
            for (int bb = 0; bb < 4; bb++) {
                uint32_t b0, b1, b2, b3;
                ldsm4(sB + SWZ((uint32_t)((wn * 64 + bb * 16 + l15) * 128) + ks * 32 + kcb), b0, b1, b2, b3);
                mma16816(ct[0][2 * bb],     a0[0], a0[1], a0[2], a0[3], b0, b2);
                mma16816(ct[0][2 * bb + 1], a0[0], a0[1], a0[2], a0[3], b1, b3);
                mma16816(ct[1][2 * bb],     a1[0], a1[1], a1[2], a1[3], b0, b2);
                mma16816(ct[1][2 * bb + 1], a1[0], a1[1], a1[2], a1[3], b1, b3);
            }
        }
        __syncthreads();
        int nc = kt + NSTAGE - 1;
        if (nc < KT) {
            uint32_t dA = sb + (nc % NSTAGE) * STAGE_B, dB = dA + 16384;
            int ko = nc * 64;
#pragma unroll
            for (int i = 0; i < 4; i++) { CP16(dA + swz[i], asrc[i] + ko); CP16(dB + swz[i], bsrc[i] + ko); }
        }
        CPCOMMIT();
    }

#pragma unroll
    for (int mi = 0; mi < 2; mi++) {
        int row = m0 + wm * 32 + mi * 16 + (lane >> 2);
#pragma unroll
        for (int ni = 0; ni < 8; ni++) {
            int col = n0 + wn * 64 + ni * 8 + (lane & 3) * 2;
            if (row < nrows)
                *(float2*)(C + (size_t)row * HID + col) = make_float2(ct[mi][ni][0], ct[mi][ni][1]);
            if (row + 8 < nrows)
                *(float2*)(C + (size_t)(row + 8) * HID + col) = make_float2(ct[mi][ni][2], ct[mi][ni][3]);
        }
    }
}

// ---------------- combine ----------------
__global__ void combine_kernel(float* __restrict__ out) {
    size_t idx = (size_t)blockIdx.x * 256 + threadIdx.x;
    int t = (int)(idx >> 11);
    int h = (int)(idx & 2047);
    float v = g_sout[idx];
#pragma unroll
    for (int k = 0; k < TOPK; k++) {
        int e = g_te[t * TOPK + k];
        int s = g_slot[t * TOPK + k];
        float w = g_tw[t * TOPK + k];
        v = fmaf(w, g_ysc[((size_t)e * T_TOK + s) * HID + h], v);
    }
    out[idx] = v;
}

extern "C" void kernel_launch(void* const* d_in, const int* in_sizes, int n_in,
                              void* d_out, int out_size) {
    const float* x   = (const float*)d_in[0];
    const float* Wg  = (const float*)d_in[1];
    const float* W1  = (const float*)d_in[2];
    const float* W2  = (const float*)d_in[3];
    const float* Wsg = (const float*)d_in[4];
    const float* Wsd = (const float*)d_in[5];
    float* out = (float*)d_out;

    cudaFuncSetAttribute(gemm1_mma, cudaFuncAttributeMaxDynamicSharedMemorySize, SMEM_DYN);
    cudaFuncSetAttribute(gemm2_mma, cudaFuncAttributeMaxDynamicSharedMemorySize, SMEM_DYN);

    __half* w1h; __half* w2h; __half* wsgh; __half* wsdh;
    cudaGetSymbolAddress((void**)&w1h, g_w1h);
    cudaGetSymbolAddress((void**)&w2h, g_w2h);
    cudaGetSymbolAddress((void**)&wsgh, g_wsgh);
    cudaGetSymbolAddress((void**)&wsdh, g_wsdh);

    const int NG_SH = (ISH / 64) * (T_TOK / 128);              // 352
    const int NG_E8 = (IEXP / 64) * (T_TOK / 128) * 8;         // 1408 (8 experts)
    const int NC    = 1024;

    zero_kernel<<<1, 32>>>();
    router_kernel<<<T_TOK + NCR, 128>>>(x, Wg, Wsg, wsgh);
    // A: shared gemm1 + conv W1[experts 0..7]
    gemm1_mma<<<NG_SH + NC, 256, SMEM_DYN>>>(1, 0, NG_SH, NC,
                                             W1, w1h, W1_HALF, nullptr, nullptr, 0);
    // B1: expert gemm1 e=0..7 + conv W1[experts 8..15]
    gemm1_mma<<<NG_E8 + NC, 256, SMEM_DYN>>>(0, 0, NG_E8, NC,
                                             W1 + W1_HALF, w1h + W1_HALF, W1_HALF,
                                             nullptr, nullptr, 0);
    // B2: expert gemm1 e=8..15 + conv W2 + conv Wsd
    gemm1_mma<<<NG_E8 + NC, 256, SMEM_DYN>>>(0, 8, NG_E8, NC,
                                             W2, w2h, W2_ELEMS,
                                             Wsd, wsdh, WSD_ELEMS);
    // C: combined gemm2 (shared blocks first, then experts)
    gemm2_mma<<<G2_SH_BLK + G2_EX_BLK, 256, SMEM_DYN>>>();
    combine_kernel<<<(T_TOK * HID) / 256, 256>>>(out);
}

// round 12
// speedup vs baseline: 1.0570x; 1.0570x over previous
#include <cuda_runtime.h>
#include <cuda_fp16.h>
#include <math.h>
#include <stdint.h>

#define T_TOK 1024
#define HID   2048
#define NEXP  16
#define TOPK  4
#define IEXP  1408
#define ISH   2816

#define W1_ELEMS  ((size_t)NEXP * 2 * IEXP * HID)
#define W2_ELEMS  ((size_t)NEXP * HID * IEXP)
#define WSG_ELEMS ((size_t)2 * ISH * HID)
#define WSD_ELEMS ((size_t)HID * ISH)

// ---------------- scratch (__device__ globals) ----------------
__device__ __align__(1024) __half g_w1h[W1_ELEMS];
__device__ __align__(1024) __half g_w2h[W2_ELEMS];
__device__ __align__(1024) __half g_wsgh[WSG_ELEMS];
__device__ __align__(1024) __half g_wsdh[WSD_ELEMS];
__device__ __align__(1024) __half g_xh[(size_t)T_TOK * HID];
__device__ __align__(1024) __half g_xg[(size_t)NEXP * T_TOK * HID];
__device__ __align__(1024) __half g_acth[(size_t)NEXP * T_TOK * IEXP];
__device__ __align__(1024) __half g_ashh[(size_t)T_TOK * ISH];
__device__ float g_ysc[(size_t)NEXP * T_TOK * HID];
__device__ float g_sout[(size_t)T_TOK * HID];
__device__ int   g_cnt[NEXP];
__device__ int   g_te[T_TOK * TOPK];
__device__ int   g_slot[T_TOK * TOPK];
__device__ float g_tw[T_TOK * TOPK];

// ---------------- PTX helpers ----------------
__device__ __forceinline__ uint32_t smem_u32(const void* p) {
    uint32_t a;
    asm("{ .reg .u64 t; cvta.to.shared.u64 t, %1; cvt.u32.u64 %0, t; }" : "=r"(a) : "l"(p));
    return a;
}
#define CP16(dst, src) asm volatile("cp.async.cg.shared.global [%0], [%1], 16;" :: "r"(dst), "l"(src) : "memory")
#define CPCOMMIT()     asm volatile("cp.async.commit_group;" ::: "memory")
#define CPWAIT(n)      asm volatile("cp.async.wait_group %0;" :: "n"(n) : "memory")

__device__ __forceinline__ void ldsm4(uint32_t addr, uint32_t& r0, uint32_t& r1,
                                      uint32_t& r2, uint32_t& r3) {
    asm volatile("ldmatrix.sync.aligned.m8n8.x4.shared.b16 {%0,%1,%2,%3}, [%4];"
                 : "=r"(r0), "=r"(r1), "=r"(r2), "=r"(r3) : "r"(addr));
}
__device__ __forceinline__ void mma16816(float* c, uint32_t a0, uint32_t a1, uint32_t a2,
                                         uint32_t a3, uint32_t b0, uint32_t b1) {
    asm volatile(
        "mma.sync.aligned.m16n8k16.row.col.f32.f16.f16.f32 "
        "{%0,%1,%2,%3}, {%4,%5,%6,%7}, {%8,%9}, {%0,%1,%2,%3};"
        : "+f"(c[0]), "+f"(c[1]), "+f"(c[2]), "+f"(c[3])
        : "r"(a0), "r"(a1), "r"(a2), "r"(a3), "r"(b0), "r"(b1));
}

#define SWZ(o) ((o) ^ (((o) >> 3) & 0x70))
#define NSTAGE 3
#define STAGE_B 32768
#define SMEM_DYN (NSTAGE * STAGE_B + 1024)

// convert 8 fp32 (held in regs) -> 8 fp16, store 16B to gmem
__device__ __forceinline__ void cvt8w(__half* d, const float4& a, const float4& b) {
    __half2 h0 = __floats2half2_rn(a.x, a.y), h1 = __floats2half2_rn(a.z, a.w);
    __half2 h2 = __floats2half2_rn(b.x, b.y), h3 = __floats2half2_rn(b.z, b.w);
    uint4 o;
    o.x = *(uint32_t*)&h0; o.y = *(uint32_t*)&h1; o.z = *(uint32_t*)&h2; o.w = *(uint32_t*)&h3;
    *(uint4*)d = o;
}

// conv role: two fp32 source regions (a then b), MLP-4 pipelined loop, 256 threads
__device__ void conv_role(int cblk, int NC,
                          const float* __restrict__ ca, __half* __restrict__ cda, size_t na,
                          const float* __restrict__ cb, __half* __restrict__ cdb, size_t nb) {
    size_t total = na + nb;
    size_t chunk = ((total + (size_t)NC * 2048 - 1) / ((size_t)NC * 2048)) * 2048;
    size_t start = (size_t)cblk * chunk;
    size_t end = start + chunk; if (end > total) end = total;
    size_t off = start + threadIdx.x * 8;
    // main: 4 points (stride 2048) in flight
    for (; off + 6144 < end; off += 8192) {
        float4 xa[4], xb[4];
#pragma unroll
        for (int u = 0; u < 4; u++) {
            size_t o = off + (size_t)u * 2048;
            const float* s = (o < na) ? (ca + o) : (cb + (o - na));
            xa[u] = *(const float4*)s;
            xb[u] = *(const float4*)(s + 4);
        }
#pragma unroll
        for (int u = 0; u < 4; u++) {
            size_t o = off + (size_t)u * 2048;
            __half* d = (o < na) ? (cda + o) : (cdb + (o - na));
            cvt8w(d, xa[u], xb[u]);
        }
    }
    for (; off < end; off += 2048) {
        const float* s = (off < na) ? (ca + off) : (cb + (off - na));
        float4 a = *(const float4*)s;
        float4 b = *(const float4*)(s + 4);
        __half* d = (off < na) ? (cda + off) : (cdb + (off - na));
        cvt8w(d, a, b);
    }
}

__global__ void zero_kernel() { if (threadIdx.x < NEXP) g_cnt[threadIdx.x] = 0; }

// ---------------- router (+x->fp16+gather) with conv(Wsg) blocks appended ----------------
#define NCR 192
__global__ void router_kernel(const float* __restrict__ x, const float* __restrict__ Wg,
                              const float* __restrict__ Wsg, __half* __restrict__ wsgh) {
    if (blockIdx.x >= T_TOK) {
        int cb = blockIdx.x - T_TOK;
        size_t chunk = ((WSG_ELEMS + (size_t)NCR * 1024 - 1) / ((size_t)NCR * 1024)) * 1024;
        size_t start = (size_t)cb * chunk;
        size_t end = start + chunk; if (end > WSG_ELEMS) end = WSG_ELEMS;
        size_t off = start + threadIdx.x * 8;
        for (; off + 3072 < end; off += 4096) {
            float4 xa[4], xb[4];
#pragma unroll
            for (int u = 0; u < 4; u++) {
                const float* s = Wsg + off + (size_t)u * 1024;
                xa[u] = *(const float4*)s; xb[u] = *(const float4*)(s + 4);
            }
#pragma unroll
            for (int u = 0; u < 4; u++)
                cvt8w(wsgh + off + (size_t)u * 1024, xa[u], xb[u]);
        }
        for (; off < end; off += 1024) {
            float4 a = *(const float4*)(Wsg + off);
            float4 b = *(const float4*)(Wsg + off + 4);
            cvt8w(wsgh + off, a, b);
        }
        return;
    }
    int t = blockIdx.x;
    const float* xr = x + (size_t)t * HID;
    float acc[NEXP];
#pragma unroll
    for (int e = 0; e < NEXP; e++) acc[e] = 0.f;
    for (int h = threadIdx.x; h < HID; h += 128) {
        float xv = xr[h];
        const float* wr = Wg + (size_t)h * NEXP;
#pragma unroll
        for (int e = 0; e < NEXP; e++) acc[e] = fmaf(xv, wr[e], acc[e]);
    }
    __shared__ float red[128 * NEXP];
#pragma unroll
    for (int e = 0; e < NEXP; e++) red[threadIdx.x * NEXP + e] = acc[e];
    __syncthreads();
    __shared__ float logits[NEXP];
    if (threadIdx.x < NEXP) {
        float s = 0.f;
        for (int i = 0; i < 128; i++) s += red[i * NEXP + threadIdx.x];
        logits[threadIdx.x] = s;
    }
    __syncthreads();
    __shared__ int s_e[TOPK], s_sl[TOPK];
    if (threadIdx.x == 0) {
        float lv[NEXP];
#pragma unroll
        for (int e = 0; e < NEXP; e++) lv[e] = logits[e];
        int ids[TOPK]; float vals[TOPK];
        bool used[NEXP];
#pragma unroll
        for (int e = 0; e < NEXP; e++) used[e] = false;
        for (int k = 0; k < TOPK; k++) {
            int bi = 0; float bv = -3.4e38f;
            for (int e = 0; e < NEXP; e++)
                if (!used[e] && lv[e] > bv) { bv = lv[e]; bi = e; }
            used[bi] = true; ids[k] = bi; vals[k] = bv;
        }
        float m = vals[0], ssum = 0.f, wv[TOPK];
        for (int k = 0; k < TOPK; k++) { wv[k] = expf(vals[k] - m); ssum += wv[k]; }
        float inv = 1.f / ssum;
        for (int k = 0; k < TOPK; k++) {
            int e = ids[k];
            int slot = atomicAdd(&g_cnt[e], 1);
            g_te[t * TOPK + k]   = e;
            g_slot[t * TOPK + k] = slot;
            g_tw[t * TOPK + k]   = wv[k] * inv;
            s_e[k] = e; s_sl[k] = slot;
        }
    }
    __syncthreads();
    int tid = threadIdx.x;
    const float4* xr4 = (const float4*)xr;
    float4 f0 = xr4[tid * 4 + 0], f1 = xr4[tid * 4 + 1];
    float4 f2 = xr4[tid * 4 + 2], f3 = xr4[tid * 4 + 3];
    __half2 h0 = __floats2half2_rn(f0.x, f0.y), h1 = __floats2half2_rn(f0.z, f0.w);
    __half2 h2 = __floats2half2_rn(f1.x, f1.y), h3 = __floats2half2_rn(f1.z, f1.w);
    __half2 h4 = __floats2half2_rn(f2.x, f2.y), h5 = __floats2half2_rn(f2.z, f2.w);
    __half2 h6 = __floats2half2_rn(f3.x, f3.y), h7 = __floats2half2_rn(f3.z, f3.w);
    uint4 u0 = make_uint4(*(uint32_t*)&h0, *(uint32_t*)&h1, *(uint32_t*)&h2, *(uint32_t*)&h3);
    uint4 u1 = make_uint4(*(uint32_t*)&h4, *(uint32_t*)&h5, *(uint32_t*)&h6, *(uint32_t*)&h7);
    uint4* dh = (uint4*)(g_xh + (size_t)t * HID) + tid * 2;
    dh[0] = u0; dh[1] = u1;
#pragma unroll
    for (int k = 0; k < TOPK; k++) {
        uint4* dg = (uint4*)(g_xg + ((size_t)s_e[k] * T_TOK + s_sl[k]) * HID) + tid * 2;
        dg[0] = u0; dg[1] = u1;
    }
}

// ---------------- gemm1 carrier: fp16 GEMM blocks + Bresenham-interleaved conv blocks ------
__global__ void __launch_bounds__(256) gemm1_mma(int shared_mode, int NG, int NC,
                                                 const float* __restrict__ ca, __half* __restrict__ cda, size_t na,
                                                 const float* __restrict__ cb, __half* __restrict__ cdb, size_t nb) {
    uint32_t bx = blockIdx.x;
    uint32_t N = (uint32_t)(NG + NC);
    uint32_t cle = (uint32_t)(((uint64_t)(bx + 1) * (uint32_t)NC) / N);
    uint32_t clt = (uint32_t)(((uint64_t)bx * (uint32_t)NC) / N);
    if (cle > clt) {
        conv_role((int)clt, NC, ca, cda, na, cb, cdb, nb);
        return;
    }
    uint32_t gidx = bx - cle;

    const __half* A; const __half* B; __half* act;
    int nrows, Ihalf;
    const int K = HID;
    int JX = shared_mode ? (ISH / 64) : (IEXP / 64);
    int gx = (int)(gidx % (uint32_t)JX);
    uint32_t rem = gidx / (uint32_t)JX;
    int gy = (int)(rem & 7);
    if (shared_mode) {
        A = g_xh; B = g_wsgh; act = g_ashh; nrows = T_TOK; Ihalf = ISH;
    } else {
        int e = (int)(rem >> 3);
        A = g_xg + (size_t)e * T_TOK * HID;
        B = g_w1h + (size_t)e * 2 * IEXP * HID;
        act = g_acth + (size_t)e * T_TOK * IEXP;
        nrows = g_cnt[e]; Ihalf = IEXP;
    }
    int m0 = gy * 128;
    if (m0 >= nrows) return;
    int j0 = gx * 64;

    extern __shared__ char smraw[];
    uint32_t sb = (smem_u32(smraw) + 1023) & ~1023u;
    int tid = threadIdx.x, lane = tid & 31, wid = tid >> 5;
    int wm = wid & 3, wn = wid >> 2;

    const __half* asrc[4]; const __half* bsrc[4]; uint32_t swz[4];
#pragma unroll
    for (int i = 0; i < 4; i++) {
        int row = (tid >> 3) + 32 * i;
        int c16 = tid & 7;
        asrc[i] = A + (size_t)(m0 + row) * K + c16 * 8;
        int brow = (row < 64) ? (j0 + row) : (Ihalf + j0 + row - 64);
        bsrc[i] = B + (size_t)brow * K + c16 * 8;
        swz[i] = SWZ((uint32_t)(row * 128 + c16 * 16));
    }

    const int KT = K / 64;
    for (int s = 0; s < NSTAGE - 1; s++) {
        uint32_t sA = sb + s * STAGE_B, sB = sA + 16384;
        int ko = s * 64;
#pragma unroll
        for (int i = 0; i < 4; i++) { CP16(sA + swz[i], asrc[i] + ko); CP16(sB + swz[i], bsrc[i] + ko); }
        CPCOMMIT();
    }

    float ct[2][8][4];
#pragma unroll
    for (int mi = 0; mi < 2; mi++)
#pragma unroll
        for (int j = 0; j < 8; j++)
#pragma unroll
            for (int q = 0; q < 4; q++) ct[mi][j][q] = 0.f;

    uint32_t l15 = (uint32_t)(lane & 15);
    uint32_t kcb = ((lane >> 4) << 4);

    for (int kt = 0; kt < KT; kt++) {
        CPWAIT(1);
        __syncthreads();
        uint32_t sA = sb + (kt % NSTAGE) * STAGE_B, sB = sA + 16384;
#pragma unroll
        for (int ks = 0; ks < 4; ks++) {
            uint32_t a0[4], a1[4];
            ldsm4(sA + SWZ((uint32_t)((wm * 32 + l15) * 128) + ks * 32 + kcb), a0[0], a0[1], a0[2], a0[3]);
            ldsm4(sA + SWZ((uint32_t)((wm * 32 + 16 + l15) * 128) + ks * 32 + kcb), a1[0], a1[1], a1[2], a1[3]);
#pragma unroll
            for (int bb = 0; bb < 2; bb++) {
                uint32_t b0, b1, b2, b3;
                ldsm4(sB + SWZ((uint32_t)((wn * 32 + bb * 16 + l15) * 128) + ks * 32 + kcb), b0, b1, b2, b3);
                mma16816(ct[0][2 * bb],     a0[0], a0[1], a0[2], a0[3], b0, b2);
                mma16816(ct[0][2 * bb + 1], a0[0], a0[1], a0[2], a0[3], b1, b3);
                mma16816(ct[1][2 * bb],     a1[0], a1[1], a1[2], a1[3], b0, b2);
                mma16816(ct[1][2 * bb + 1], a1[0], a1[1], a1[2], a1[3], b1, b3);
            }
#pragma unroll
            for (int bb = 0; bb < 2; bb++) {
                uint32_t b0, b1, b2, b3;
                ldsm4(sB + SWZ((uint32_t)((64 + wn * 32 + bb * 16 + l15) * 128) + ks * 32 + kcb), b0, b1, b2, b3);
                mma16816(ct[0][4 + 2 * bb],     a0[0], a0[1], a0[2], a0[3], b0, b2);
                mma16816(ct[0][4 + 2 * bb + 1], a0[0], a0[1], a0[2], a0[3], b1, b3);
                mma16816(ct[1][4 + 2 * bb],     a1[0], a1[1], a1[2], a1[3], b0, b2);
                mma16816(ct[1][4 + 2 * bb + 1], a1[0], a1[1], a1[2], a1[3], b1, b3);
            }
        }
        __syncthreads();
        int nc = kt + NSTAGE - 1;
        if (nc < KT) {
            uint32_t dA = sb + (nc % NSTAGE) * STAGE_B, dB = dA + 16384;
            int ko = nc * 64;
#pragma unroll
            for (int i = 0; i < 4; i++) { CP16(dA + swz[i], asrc[i] + ko); CP16(dB + swz[i], bsrc[i] + ko); }
        }
        CPCOMMIT();
    }

#pragma unroll
    for (int mi = 0; mi < 2; mi++) {
        int row = m0 + wm * 32 + mi * 16 + (lane >> 2);
#pragma unroll
        for (int ni = 0; ni < 4; ni++) {
            int col = j0 + wn * 32 + ni * 8 + (lane & 3) * 2;
            if (row < nrows) {
                float g0 = ct[mi][ni][0], g1 = ct[mi][ni][1];
                float u0 = ct[mi][ni + 4][0], u1 = ct[mi][ni + 4][1];
                __half2 h = __floats2half2_rn(g0 / (1.f + expf(-g0)) * u0,
                                              g1 / (1.f + expf(-g1)) * u1);
                *(__half2*)(act + (size_t)row * Ihalf + col) = h;
            }
            if (row + 8 < nrows) {
                float g0 = ct[mi][ni][2], g1 = ct[mi][ni][3];
                float u0 = ct[mi][ni + 4][2], u1 = ct[mi][ni + 4][3];
                __half2 h = __floats2half2_rn(g0 / (1.f + expf(-g0)) * u0,
                                              g1 / (1.f + expf(-g1)) * u1);
                *(__half2*)(act + (size_t)(row + 8) * Ihalf + col) = h;
            }
        }
    }
}

// ---------------- gemm2 combined: flattened grid = 128 shared blocks + 2048 expert blocks ----
#define G2_SH_BLK ((HID / 128) * (T_TOK / 128))
#define G2_EX_BLK ((HID / 128) * (T_TOK / 128) * NEXP)
__global__ void __launch_bounds__(256) gemm2_mma() {
    uint32_t bx = blockIdx.x;
    const __half* A; const __half* B; float* C;
    int nrows, K, gx, gy;
    if (bx < G2_SH_BLK) {
        A = g_ashh; B = g_wsdh; C = g_sout; nrows = T_TOK; K = ISH;
        gx = (int)(bx & 15); gy = (int)(bx >> 4);
    } else {
        uint32_t i = bx - G2_SH_BLK;
        gx = (int)(i & 15);
        uint32_t rem = i >> 4;
        gy = (int)(rem & 7);
        int e = (int)(rem >> 3);
        A = g_acth + (size_t)e * T_TOK * IEXP;
        B = g_w2h + (size_t)e * HID * IEXP;
        C = g_ysc + (size_t)e * T_TOK * HID;
        nrows = g_cnt[e]; K = IEXP;
    }
    int m0 = gy * 128;
    if (m0 >= nrows) return;
    int n0 = gx * 128;

    extern __shared__ char smraw[];
    uint32_t sb = (smem_u32(smraw) + 1023) & ~1023u;
    int tid = threadIdx.x, lane = tid & 31, wid = tid >> 5;
    int wm = wid & 3, wn = wid >> 2;

    const __half* asrc[4]; const __half* bsrc[4]; uint32_t swz[4];
#pragma unroll
    for (int i = 0; i < 4; i++) {
        int row = (tid >> 3) + 32 * i;
        int c16 = tid & 7;
        asrc[i] = A + (size_t)(m0 + row) * K + c16 * 8;
        bsrc[i] = B + (size_t)(n0 + row) * K + c16 * 8;
        swz[i] = SWZ((uint32_t)(row * 128 + c16 * 16));
    }

    const int KT = K / 64;
    for (int s = 0; s < NSTAGE - 1; s++) {
        uint32_t sA = sb + s * STAGE_B, sB = sA + 16384;
        int ko = s * 64;
#pragma unroll
        for (int i = 0; i < 4; i++) { CP16(sA + swz[i], asrc[i] + ko); CP16(sB + swz[i], bsrc[i] + ko); }
        CPCOMMIT();
    }

    float ct[2][8][4];
#pragma unroll
    for (int mi = 0; mi < 2; mi++)
#pragma unroll
        for (int j = 0; j < 8; j++)
#pragma unroll
            for (int q = 0; q < 4; q++) ct[mi][j][q] = 0.f;

    uint32_t l15 = (uint32_t)(lane & 15);
    uint32_t kcb = ((lane >> 4) << 4);

    for (int kt = 0; kt < KT; kt++) {
        CPWAIT(1);
        __syncthreads();
        uint32_t sA = sb + (kt % NSTAGE) * STAGE_B, sB = sA + 16384;
#pragma unroll
        for (int ks = 0; ks < 4; ks++) {
            uint32_t a0[4], a1[4];
            ldsm4(sA + SWZ((uint32_t)((wm * 32 + l15) * 128) + ks * 32 + kcb), a0[0], a0[1], a0[2], a0[3]);
            ldsm4(sA + SWZ((uint32_t)((wm * 32 + 16 + l15) * 128) + ks * 32 + kcb), a1[0], a1[1], a1[2], a1[3]);
#pragma unroll
            for (int bb = 0; bb < 4; bb++) {
                uint32_t b0, b1, b2, b3;
                ldsm4(sB + SWZ((uint32_t)((wn * 64 + bb * 16 + l15) * 128) + ks * 32 + kcb), b0, b1, b2, b3);
                mma16816(ct[0][2 * bb],     a0[0], a0[1], a0[2], a0[3], b0, b2);
                mma16816(ct[0][2 * bb + 1], a0[0], a0[1], a0[2], a0[3], b1, b3);
                mma16816(ct[1][2 * bb],     a1[0], a1[1], a1[2], a1[3], b0, b2);
                mma16816(ct[1][2 * bb + 1], a1[0], a1[1], a1[2], a1[3], b1, b3);
            }
        }
        __syncthreads();
        int nc = kt + NSTAGE - 1;
        if (nc < KT) {
            uint32_t dA = sb + (nc % NSTAGE) * STAGE_B, dB = dA + 16384;
            int ko = nc * 64;
#pragma unroll
            for (int i = 0; i < 4; i++) { CP16(dA + swz[i], asrc[i] + ko); CP16(dB + swz[i], bsrc[i] + ko); }
        }
        CPCOMMIT();
    }

#pragma unroll
    for (int mi = 0; mi < 2; mi++) {
        int row = m0 + wm * 32 + mi * 16 + (lane >> 2);
#pragma unroll
        for (int ni = 0; ni < 8; ni++) {
            int col = n0 + wn * 64 + ni * 8 + (lane & 3) * 2;
            if (row < nrows)
                *(float2*)(C + (size_t)row * HID + col) = make_float2(ct[mi][ni][0], ct[mi][ni][1]);
            if (row + 8 < nrows)
                *(float2*)(C + (size_t)(row + 8) * HID + col) = make_float2(ct[mi][ni][2], ct[mi][ni][3]);
        }
    }
}

// ---------------- combine ----------------
__global__ void combine_kernel(float* __restrict__ out) {
    size_t idx = (size_t)blockIdx.x * 256 + threadIdx.x;
    int t = (int)(idx >> 11);
    int h = (int)(idx & 2047);
    float v = g_sout[idx];
#pragma unroll
    for (int k = 0; k < TOPK; k++) {
        int e = g_te[t * TOPK + k];
        int s = g_slot[t * TOPK + k];
        float w = g_tw[t * TOPK + k];
        v = fmaf(w, g_ysc[((size_t)e * T_TOK + s) * HID + h], v);
    }
    out[idx] = v;
}

extern "C" void kernel_launch(void* const* d_in, const int* in_sizes, int n_in,
                              void* d_out, int out_size) {
    const float* x   = (const float*)d_in[0];
    const float* Wg  = (const float*)d_in[1];
    const float* W1  = (const float*)d_in[2];
    const float* W2  = (const float*)d_in[3];
    const float* Wsg = (const float*)d_in[4];
    const float* Wsd = (const float*)d_in[5];
    float* out = (float*)d_out;

    cudaFuncSetAttribute(gemm1_mma, cudaFuncAttributeMaxDynamicSharedMemorySize, SMEM_DYN);
    cudaFuncSetAttribute(gemm2_mma, cudaFuncAttributeMaxDynamicSharedMemorySize, SMEM_DYN);

    __half* w1h; __half* w2h; __half* wsgh; __half* wsdh;
    cudaGetSymbolAddress((void**)&w1h, g_w1h);
    cudaGetSymbolAddress((void**)&w2h, g_w2h);
    cudaGetSymbolAddress((void**)&wsgh, g_wsgh);
    cudaGetSymbolAddress((void**)&wsdh, g_wsdh);

    const int NG_SH = (ISH / 64) * (T_TOK / 128);              // 352
    const int NG_EX = (IEXP / 64) * (T_TOK / 128) * NEXP;      // 2816
    const int NC_A  = 1024;
    const int NC_B  = 512;

    zero_kernel<<<1, 32>>>();
    router_kernel<<<T_TOK + NCR, 128>>>(x, Wg, Wsg, wsgh);
    // A: shared gemm1 + conv of ALL W1
    gemm1_mma<<<NG_SH + NC_A, 256, SMEM_DYN>>>(1, NG_SH, NC_A,
                                               W1, w1h, W1_ELEMS, nullptr, nullptr, 0);
    // B: all-expert gemm1 + conv W2 + conv Wsd
    gemm1_mma<<<NG_EX + NC_B, 256, SMEM_DYN>>>(0, NG_EX, NC_B,
                                               W2, w2h, W2_ELEMS, Wsd, wsdh, WSD_ELEMS);
    // C: combined gemm2 (shared blocks first)
    gemm2_mma<<<G2_SH_BLK + G2_EX_BLK, 256, SMEM_DYN>>>();
    combine_kernel<<<(T_TOK * HID) / 256, 256>>>(out);
}